// round 3
// baseline (speedup 1.0000x reference)
#include <cuda_runtime.h>
#include <math.h>

#define BATCH 4
#define CDIM  256
#define HDIM  128
#define WDIM  128
#define HW    (HDIM*WDIM)
#define KTOP  100

// conv tiling
#define TW  32
#define TH  8
#define OCT 64
#define SS  35   // smem patch row stride (pad 34 -> 35 for conflict-free LDS)

// ---------------- scratch (device globals; no allocations allowed) --------
__device__ float g_feat[BATCH*CDIM*HW];     // 64 MB
__device__ float g_h   [BATCH*CDIM*HW];     // 64 MB
__device__ float g_score[BATCH*HW];
__device__ float g_tk_score[BATCH*KTOP];
__device__ int   g_tk_idx  [BATCH*KTOP];
__device__ float g_bns[2][CDIM];
__device__ float g_bnb[2][CDIM];

// ---------------- fold BN into per-channel scale/bias ---------------------
__global__ void prep_bn_kernel(const float* g1,const float* b1,const float* m1,const float* v1,
                               const float* g2,const float* b2,const float* m2,const float* v2){
    int c = threadIdx.x;
    float s1 = g1[c]*rsqrtf(v1[c]+1e-5f);
    g_bns[0][c]=s1; g_bnb[0][c]=b1[c]-m1[c]*s1;
    float s2 = g2[c]*rsqrtf(v2[c]+1e-5f);
    g_bns[1][c]=s2; g_bnb[1][c]=b2[c]-m2[c]*s2;
}

// ---------------- conv3x3 + BN + ReLU (direct, fp32) ----------------------
// block tile: 64 out-channels x (32x8) pixels; thread tile: 8 oc x 8 px
// which==0: in=bev(ext), out=g_feat, bn1.  which==1: in=g_feat, out=g_h, bn2.
__global__ __launch_bounds__(256,2)
void conv3x3_bn_relu_kernel(const float* __restrict__ in_ext,
                            const float* __restrict__ wgt,
                            int which)
{
    const float* in  = which ? g_feat : in_ext;
    float*       out = which ? g_h    : g_feat;

    __shared__ float s_in[(TH+2)*SS];   // 350 floats
    __shared__ float s_w [OCT*9];       // 576 floats

    const int b       = blockIdx.z;
    const int oc_base = blockIdx.y*OCT;
    const int tile    = blockIdx.x;
    const int tx0 = (tile & 3)*TW;
    const int ty0 = (tile >> 2)*TH;
    const int t    = threadIdx.x;
    const int ocg  = t >> 5;          // 0..7  (== warp id -> weight reads broadcast)
    const int pxg  = t & 31;
    const int prow = pxg & 7;         // 0..7
    const int pcb  = (pxg >> 3) << 3; // 0,8,16,24

    const float* in_b = in + (size_t)b*CDIM*HW;

    // precompute patch load slots (2 per thread, 350 total)
    int li0 = t, li1 = t + 256;
    int p_goff0 = -1, p_goff1 = -1;
    {
        int r = li0/SS, c0 = li0%SS;
        int gy = ty0-1+r, gx = tx0-1+c0;
        if (c0<34 && gy>=0 && gy<HDIM && gx>=0 && gx<WDIM) p_goff0 = gy*WDIM+gx;
    }
    if (li1 < (TH+2)*SS) {
        int r = li1/SS, c0 = li1%SS;
        int gy = ty0-1+r, gx = tx0-1+c0;
        if (c0<34 && gy>=0 && gy<HDIM && gx>=0 && gx<WDIM) p_goff1 = gy*WDIM+gx;
    } else li1 = -1;

    // weight load slots (up to 3 per thread, 576 total)
    const int wi0=t, wi1=t+256;
    const int wi2 = (t<64) ? t+512 : -1;
    const size_t w_goff0 = (size_t)(oc_base + wi0/9)*(CDIM*9) + (wi0%9);
    const size_t w_goff1 = (size_t)(oc_base + wi1/9)*(CDIM*9) + (wi1%9);
    const size_t w_goff2 = (wi2>=0) ? (size_t)(oc_base + wi2/9)*(CDIM*9) + (wi2%9) : 0;

    float acc[8][8];
    #pragma unroll
    for (int i=0;i<8;i++)
        #pragma unroll
        for (int j=0;j<8;j++) acc[i][j]=0.f;

    // fill ic=0
    s_in[li0] = (p_goff0>=0) ? in_b[p_goff0] : 0.f;
    if (li1>=0) s_in[li1] = (p_goff1>=0) ? in_b[p_goff1] : 0.f;
    s_w[wi0] = wgt[w_goff0];
    s_w[wi1] = wgt[w_goff1];
    if (wi2>=0) s_w[wi2] = wgt[w_goff2];
    __syncthreads();

    for (int ic=0; ic<CDIM; ic++){
        // prefetch next ic into registers (overlaps with compute below)
        float p0=0.f,p1=0.f,w0=0.f,w1=0.f,w2=0.f;
        if (ic < CDIM-1){
            const float* ip = in_b + (size_t)(ic+1)*HW;
            if (p_goff0>=0) p0 = ip[p_goff0];
            if (li1>=0 && p_goff1>=0) p1 = ip[p_goff1];
            const float* wp = wgt + (size_t)(ic+1)*9;
            w0 = wp[w_goff0]; w1 = wp[w_goff1];
            if (wi2>=0) w2 = wp[w_goff2];
        }
        // 9-tap accumulate from smem
        #pragma unroll
        for (int ky=0; ky<3; ky++){
            float rin[10];
            #pragma unroll
            for (int j=0;j<10;j++) rin[j] = s_in[(prow+ky)*SS + pcb + j];
            #pragma unroll
            for (int kx=0;kx<3;kx++){
                float wv[8];
                #pragma unroll
                for (int i=0;i<8;i++) wv[i] = s_w[(ocg*8+i)*9 + ky*3 + kx];
                #pragma unroll
                for (int i=0;i<8;i++)
                    #pragma unroll
                    for (int j=0;j<8;j++)
                        acc[i][j] = fmaf(wv[i], rin[j+kx], acc[i][j]);
            }
        }
        __syncthreads();
        if (ic < CDIM-1){
            s_in[li0]=p0;
            if (li1>=0) s_in[li1]=p1;
            s_w[wi0]=w0; s_w[wi1]=w1;
            if (wi2>=0) s_w[wi2]=w2;
        }
        __syncthreads();
    }

    // epilogue: BN + ReLU, vectorized stores
    const int gy  = ty0 + prow;
    const int gx0 = tx0 + pcb;
    #pragma unroll
    for (int i=0;i<8;i++){
        int oc = oc_base + ocg*8 + i;
        float sc = g_bns[which][oc], bb = g_bnb[which][oc];
        float4 v0, v1;
        v0.x = fmaxf(fmaf(acc[i][0],sc,bb),0.f);
        v0.y = fmaxf(fmaf(acc[i][1],sc,bb),0.f);
        v0.z = fmaxf(fmaf(acc[i][2],sc,bb),0.f);
        v0.w = fmaxf(fmaf(acc[i][3],sc,bb),0.f);
        v1.x = fmaxf(fmaf(acc[i][4],sc,bb),0.f);
        v1.y = fmaxf(fmaf(acc[i][5],sc,bb),0.f);
        v1.z = fmaxf(fmaf(acc[i][6],sc,bb),0.f);
        v1.w = fmaxf(fmaf(acc[i][7],sc,bb),0.f);
        float* op = out + ((size_t)(b*CDIM+oc)*HDIM + gy)*WDIM + gx0;
        *(float4*)op     = v0;
        *(float4*)(op+4) = v1;
    }
}

// ---------------- 1x1 conv + sigmoid -> heatmap ---------------------------
// block: 256 thr = 32 pixels x 8 channel-groups
__global__ void heatmap_kernel(const float* __restrict__ w2, const float* __restrict__ b2){
    int blk = blockIdx.x;             // 0 .. 2047
    int b   = blk >> 9;               // 512 blocks / batch
    int rem = blk & 511;
    int y   = rem >> 2;
    int x0  = (rem & 3) << 5;
    int lane = threadIdx.x & 31;
    int cg   = threadIdx.x >> 5;
    const float* hb = g_h + (size_t)b*CDIM*HW + (size_t)y*WDIM + x0 + lane;
    float sum = 0.f;
    #pragma unroll 8
    for (int cc=0; cc<32; cc++){
        int c = cg*32 + cc;
        sum = fmaf(hb[(size_t)c*HW], w2[c], sum);
    }
    __shared__ float red[8][33];
    red[cg][lane] = sum;
    __syncthreads();
    if (cg==0){
        float s = red[0][lane];
        #pragma unroll
        for (int i=1;i<8;i++) s += red[i][lane];
        s += b2[0];
        g_score[(size_t)b*HW + (size_t)y*WDIM + x0 + lane] = 1.f/(1.f+expf(-s));
    }
}

// ---------------- top-100 per batch (sorted desc, index-asc ties) ---------
__global__ void topk_kernel(float* __restrict__ out_score){
    const int b = blockIdx.x;
    const int t = threadIdx.x;   // 512 threads
    float v[32];
    #pragma unroll
    for (int j=0;j<32;j++) v[j] = g_score[(size_t)b*HW + j*512 + t];

    __shared__ float s_bv[16];
    __shared__ int   s_bi[16];
    __shared__ int   s_ci;

    for (int k=0;k<KTOP;k++){
        float bv = -1e30f; int bi = 0x7fffffff;
        #pragma unroll
        for (int j=0;j<32;j++){
            float x = v[j]; int idx = j*512+t;
            if (x > bv || (x==bv && idx<bi)) { bv=x; bi=idx; }
        }
        #pragma unroll
        for (int o=16;o>0;o>>=1){
            float ov = __shfl_down_sync(0xffffffffu, bv, o);
            int   oi = __shfl_down_sync(0xffffffffu, bi, o);
            if (ov > bv || (ov==bv && oi<bi)) { bv=ov; bi=oi; }
        }
        if ((t&31)==0){ s_bv[t>>5]=bv; s_bi[t>>5]=bi; }
        __syncthreads();
        if (t==0){
            float cv=s_bv[0]; int ci=s_bi[0];
            for (int w=1;w<16;w++){
                float ov=s_bv[w]; int oi=s_bi[w];
                if (ov>cv || (ov==cv && oi<ci)){cv=ov;ci=oi;}
            }
            s_ci = ci;
            g_tk_score[b*KTOP+k]=cv;
            g_tk_idx  [b*KTOP+k]=ci;
            out_score [b*KTOP+k]=cv;
        }
        __syncthreads();
        int ci = s_ci;
        if ((ci & 511) == t) v[ci>>9] = -1e30f;
        __syncthreads();
    }
}

// ---------------- gather + MLP + LN + heads + anchor ----------------------
// one block per (b,k); 256 threads
__global__ __launch_bounds__(256)
void final_kernel(const float* __restrict__ ta,
                  const float* __restrict__ fw1, const float* __restrict__ fb1,
                  const float* __restrict__ lng, const float* __restrict__ lnb,
                  const float* __restrict__ fw2, const float* __restrict__ fb2,
                  const float* __restrict__ zw,  const float* __restrict__ zb,
                  const float* __restrict__ dw,  const float* __restrict__ db,
                  const float* __restrict__ yw,  const float* __restrict__ yb,
                  const float* __restrict__ vw,  const float* __restrict__ vb,
                  float* __restrict__ out)
{
    const int blk = blockIdx.x;
    const int b = blk/KTOP, k = blk%KTOP;
    const int t = threadIdx.x;

    __shared__ float sg[CDIM];
    __shared__ float sx[CDIM];
    __shared__ float r1[8], r2[8];
    __shared__ float shead[8];

    const int   idx   = g_tk_idx  [b*KTOP+k];
    const float score = g_tk_score[b*KTOP+k];

    sg[t] = g_feat[((size_t)(b*CDIM+t))*HW + idx];
    __syncthreads();

    // x = g @ fp_w1^T + b1
    float acc = fb1[t];
    {
        const float4* wr = (const float4*)(fw1 + (size_t)t*CDIM);
        #pragma unroll 8
        for (int c4=0; c4<CDIM/4; c4++){
            float4 w = wr[c4];
            acc = fmaf(w.x, sg[c4*4+0], acc);
            acc = fmaf(w.y, sg[c4*4+1], acc);
            acc = fmaf(w.z, sg[c4*4+2], acc);
            acc = fmaf(w.w, sg[c4*4+3], acc);
        }
    }
    // LayerNorm over 256 features
    {
        float s = acc, ss = acc*acc;
        #pragma unroll
        for (int o=16;o>0;o>>=1){
            s  += __shfl_down_sync(0xffffffffu, s,  o);
            ss += __shfl_down_sync(0xffffffffu, ss, o);
        }
        if ((t&31)==0){ r1[t>>5]=s; r2[t>>5]=ss; }
    }
    __syncthreads();
    float tot=0.f, tot2=0.f;
    #pragma unroll
    for (int i=0;i<8;i++){ tot+=r1[i]; tot2+=r2[i]; }
    float mu  = tot * (1.f/CDIM);
    float var = tot2 * (1.f/CDIM) - mu*mu;
    float xn  = (acc-mu)*rsqrtf(var+1e-5f)*lng[t] + lnb[t];
    xn = fmaxf(xn, 0.f);
    sx[t] = xn;
    __syncthreads();

    // prior_feature = (x @ fp_w2^T + b2) * (1+score)
    float acc2 = fb2[t];
    {
        const float4* wr = (const float4*)(fw2 + (size_t)t*CDIM);
        #pragma unroll 8
        for (int c4=0; c4<CDIM/4; c4++){
            float4 w = wr[c4];
            acc2 = fmaf(w.x, sx[c4*4+0], acc2);
            acc2 = fmaf(w.y, sx[c4*4+1], acc2);
            acc2 = fmaf(w.z, sx[c4*4+2], acc2);
            acc2 = fmaf(w.w, sx[c4*4+3], acc2);
        }
    }
    acc2 *= (1.f + score);
    out[((size_t)(b*KTOP+k))*CDIM + t] = acc2;

    // heads: 8 dot products of sg with z/dim/yaw/vel rows (one per warp)
    {
        int w = t>>5, lane = t&31;
        const float* hw;
        if      (w==0) hw = zw;
        else if (w<4)  hw = dw + (w-1)*CDIM;
        else if (w<6)  hw = yw + (w-4)*CDIM;
        else           hw = vw + (w-6)*CDIM;
        float hs = 0.f;
        #pragma unroll
        for (int c=0;c<CDIM/32;c++) hs = fmaf(sg[c*32+lane], hw[c*32+lane], hs);
        #pragma unroll
        for (int o=16;o>0;o>>=1) hs += __shfl_down_sync(0xffffffffu, hs, o);
        if (lane==0) shead[w]=hs;
    }
    __syncthreads();

    if (t==0){
        float zp  = shead[0]+zb[0];
        float d0  = shead[1]+db[0], d1 = shead[2]+db[1], d2 = shead[3]+db[2];
        float yp0 = shead[4]+yb[0], yp1 = shead[5]+yb[1];
        float vp0 = shead[6]+vb[0], vp1 = shead[7]+vb[1];
        const float* pa = ta + ((size_t)b*900 + k)*11;
        int xs = idx & 127, ys = idx >> 7;
        float y0 = tanhf(yp0), y1 = tanhf(yp1);
        float nr = fmaxf(sqrtf(y0*y0+y1*y1), 1e-6f);
        float o0 = (xs+0.5f)*0.8f - 51.2f;
        float o1 = (ys+0.5f)*0.8f - 51.2f;
        float* oa = out + 102400 + ((size_t)(b*KTOP+k))*11;
        oa[0]=o0; oa[1]=o1;
        oa[2]=pa[2] + 0.5f*zp;
        oa[3]=pa[3] + 0.2f*fminf(fmaxf(d0,-1.f),1.f);
        oa[4]=pa[4] + 0.2f*fminf(fmaxf(d1,-1.f),1.f);
        oa[5]=pa[5] + 0.2f*fminf(fmaxf(d2,-1.f),1.f);
        oa[6]=0.7f*pa[6] + 0.3f*y0/nr;
        oa[7]=0.7f*pa[7] + 0.3f*y1/nr;
        oa[8]=pa[8] + 0.2f*fminf(fmaxf(vp0,-2.f),2.f);
        oa[9]=pa[9] + 0.2f*fminf(fmaxf(vp1,-2.f),2.f);
        oa[10]=pa[10];
    }
}

// ---------------- launch ---------------------------------------------------
extern "C" void kernel_launch(void* const* d_in, const int* in_sizes, int n_in,
                              void* d_out, int out_size)
{
    const float* bev  = (const float*)d_in[0];
    const float* ta   = (const float*)d_in[1];
    const float* sw   = (const float*)d_in[2];
    const float* bn1g = (const float*)d_in[3];
    const float* bn1b = (const float*)d_in[4];
    const float* bn1m = (const float*)d_in[5];
    const float* bn1v = (const float*)d_in[6];
    const float* ow1  = (const float*)d_in[7];
    const float* bn2g = (const float*)d_in[8];
    const float* bn2b = (const float*)d_in[9];
    const float* bn2m = (const float*)d_in[10];
    const float* bn2v = (const float*)d_in[11];
    const float* ow2  = (const float*)d_in[12];
    const float* ob2  = (const float*)d_in[13];
    const float* fw1  = (const float*)d_in[14];
    const float* fb1  = (const float*)d_in[15];
    const float* lng  = (const float*)d_in[16];
    const float* lnb  = (const float*)d_in[17];
    const float* fw2  = (const float*)d_in[18];
    const float* fb2  = (const float*)d_in[19];
    const float* zw   = (const float*)d_in[20];
    const float* zb   = (const float*)d_in[21];
    const float* dw   = (const float*)d_in[22];
    const float* db   = (const float*)d_in[23];
    const float* yw   = (const float*)d_in[24];
    const float* yb   = (const float*)d_in[25];
    const float* vw   = (const float*)d_in[26];
    const float* vb   = (const float*)d_in[27];

    float* out = (float*)d_out;

    prep_bn_kernel<<<1,256>>>(bn1g,bn1b,bn1m,bn1v, bn2g,bn2b,bn2m,bn2v);
    dim3 cgrid(64,4,4);
    conv3x3_bn_relu_kernel<<<cgrid,256>>>(bev, sw, 0);
    conv3x3_bn_relu_kernel<<<cgrid,256>>>(bev, ow1, 1);
    heatmap_kernel<<<2048,256>>>(ow2, ob2);
    topk_kernel<<<4,512>>>(out + 102400 + 4400);
    final_kernel<<<400,256>>>(ta, fw1, fb1, lng, lnb, fw2, fb2,
                              zw, zb, dw, db, yw, yb, vw, vb, out);
}

// round 5
// speedup vs baseline: 1.9449x; 1.9449x over previous
#include <cuda_runtime.h>
#include <cuda_fp16.h>
#include <cstdint>
#include <math.h>

#define BATCH 4
#define CDIM  256
#define HDIM  128
#define WDIM  128
#define HW    (HDIM*WDIM)
#define KTOP  100

#define SWZ128(o) ((o) ^ (((o) >> 3) & 0x70))

// ---------------- device globals (no allocations allowed) ------------------
__device__ __half g_bev_hi [BATCH*HW*CDIM];
__device__ __half g_bev_lo [BATCH*HW*CDIM];
__device__ __half g_feat_hi[BATCH*HW*CDIM];
__device__ __half g_feat_lo[BATCH*HW*CDIM];
// weights: [conv2][plane2][chunk4][tap9][ochalf2][8192 halfs, pre-swizzled 16KB image]
__device__ __half g_wA[2*2*4*9*2*8192];
__device__ float g_hm_part[2][BATCH*HW];
__device__ float g_tk_score[BATCH*KTOP];
__device__ int   g_tk_idx  [BATCH*KTOP];
__device__ float g_bns[2][CDIM];
__device__ float g_bnb[2][CDIM];

// ---------------- PTX helpers ----------------------------------------------
__device__ __forceinline__ uint32_t smem_to_u32(const void* p){
    uint32_t a;
    asm("{ .reg .u64 t; cvta.to.shared.u64 t, %1; cvt.u32.u64 %0, t; }" : "=r"(a) : "l"(p));
    return a;
}
__device__ __forceinline__ void cp16(uint32_t saddr, const void* g, int srcsize){
    asm volatile("cp.async.cg.shared.global [%0], [%1], 16, %2;"
        :: "r"(saddr), "l"(g), "r"(srcsize));
}
#define CP_COMMIT() asm volatile("cp.async.commit_group;")
#define CP_WAIT(n)  asm volatile("cp.async.wait_group %0;" :: "n"(n))

__device__ __forceinline__ void ldsm_x4(uint32_t* r, uint32_t addr){
    asm volatile("ldmatrix.sync.aligned.m8n8.x4.shared.b16 {%0,%1,%2,%3}, [%4];"
        : "=r"(r[0]),"=r"(r[1]),"=r"(r[2]),"=r"(r[3]) : "r"(addr));
}
__device__ __forceinline__ void ldsm_x2(uint32_t* r, uint32_t addr){
    asm volatile("ldmatrix.sync.aligned.m8n8.x2.shared.b16 {%0,%1}, [%2];"
        : "=r"(r[0]),"=r"(r[1]) : "r"(addr));
}
__device__ __forceinline__ void mma16816(float* c, const uint32_t* a, const uint32_t* b){
    asm volatile("mma.sync.aligned.m16n8k16.row.col.f32.f16.f16.f32 "
        "{%0,%1,%2,%3}, {%4,%5,%6,%7}, {%8,%9}, {%0,%1,%2,%3};"
        : "+f"(c[0]),"+f"(c[1]),"+f"(c[2]),"+f"(c[3])
        : "r"(a[0]),"r"(a[1]),"r"(a[2]),"r"(a[3]), "r"(b[0]),"r"(b[1]));
}

// ---------------- BN fold --------------------------------------------------
__global__ void prep_bn_kernel(const float* g1,const float* b1,const float* m1,const float* v1,
                               const float* g2,const float* b2,const float* m2,const float* v2){
    int c = threadIdx.x;
    float s1 = g1[c]*rsqrtf(v1[c]+1e-5f);
    g_bns[0][c]=s1; g_bnb[0][c]=b1[c]-m1[c]*s1;
    float s2 = g2[c]*rsqrtf(v2[c]+1e-5f);
    g_bns[1][c]=s2; g_bnb[1][c]=b2[c]-m2[c]*s2;
}

// ---------------- weight prep: fp16 hi/lo, pre-swizzled SMEM images --------
__global__ void prep_w_kernel(const float* __restrict__ sw, const float* __restrict__ ow1){
    int t = blockIdx.x*256 + threadIdx.x;      // 1,179,648 tasks
    int ic = t & 63;
    int oc = (t>>6) & 127;
    int u  = t >> 13;
    int half = u & 1; u >>= 1;                 // oc half (0:oc 0-127, 1:oc 128-255)
    int q = u % 9;    u /= 9;                  // tap = dy*3+dx
    int chunk = u & 3; u >>= 2;
    int conv = u;
    int dy = q/3, dx = q%3;
    const float* w = conv ? ow1 : sw;
    float val = w[(((size_t)(half*128+oc)*CDIM + chunk*64+ic)*3 + dy)*3 + dx];
    __half hi = __float2half_rn(val);
    __half lo = __float2half_rn(val - __half2float(hi));
    uint32_t swz = SWZ128((uint32_t)(oc*128 + ic*2)) >> 1;   // element in 16KB tile
    size_t base_hi = ((size_t)((((conv*2+0)*4+chunk)*9 + q)*2 + half))*8192;
    size_t base_lo = ((size_t)((((conv*2+1)*4+chunk)*9 + q)*2 + half))*8192;
    g_wA[base_hi + swz] = hi;
    g_wA[base_lo + swz] = lo;
}

// ---------------- bev transpose: [b][c][y][x] f32 -> [b][y][x][c] fp16 hi/lo
__global__ __launch_bounds__(256)
void transpose_bev_kernel(const float* __restrict__ bev){
    __shared__ __half sh[64*130];
    __shared__ __half sl[64*130];
    int y = blockIdx.x, b = blockIdx.y;
    int t = threadIdx.x;
    for (int c0 = 0; c0 < CDIM; c0 += 64){
        #pragma unroll
        for (int i=0;i<32;i++){
            int idx = t + i*256;
            int cl = idx >> 7, x = idx & 127;
            float v = bev[(((size_t)(b*CDIM + c0+cl)*HDIM + y))*WDIM + x];
            __half hi = __float2half_rn(v);
            sh[cl*130+x] = hi;
            sl[cl*130+x] = __float2half_rn(v - __half2float(hi));
        }
        __syncthreads();
        #pragma unroll
        for (int i=0;i<16;i++){
            int idx = t + i*256;          // 4096 pairs
            int cp = idx & 31, x = idx >> 5;
            int cl = cp*2;
            size_t o = (((size_t)b*HW + (size_t)y*WDIM + x)<<8) + c0 + cl;
            __half2 vh, vl;
            vh.x = sh[cl*130+x]; vh.y = sh[(cl+1)*130+x];
            vl.x = sl[cl*130+x]; vl.y = sl[(cl+1)*130+x];
            *(__half2*)(g_bev_hi + o) = vh;
            *(__half2*)(g_bev_lo + o) = vl;
        }
        __syncthreads();
    }
}

// ---------------- tensor-core (mma.sync) conv3x3 ---------------------------
// CTA: 128 oc x 128 px (one image row). 8 warps = 2(oc) x 4(px).
// K loop: 108 stages of K=64: term(3) x chunk(4) x tap(9).
// smem: 2 x (A 16KB + B 16KB) = 64KB dynamic, cp.async double-buffered.
__global__ __launch_bounds__(256,2)
void conv_mma_kernel(int which, const float* __restrict__ w2)
{
    extern __shared__ __align__(128) char smem[];
    const int t = threadIdx.x, lane = t&31, wid = t>>5;
    const int wm = wid>>2, wn = wid&3;
    const int y = blockIdx.x, ochalf = blockIdx.y, b = blockIdx.z;
    const uint32_t sb = smem_to_u32(smem);
    const __half* inH = which ? g_feat_hi : g_bev_hi;
    const __half* inL = which ? g_feat_lo : g_bev_lo;

    float acc[4][4][4];
    #pragma unroll
    for (int mi=0;mi<4;mi++)
        #pragma unroll
        for (int ni=0;ni<4;ni++)
            #pragma unroll
            for (int r=0;r<4;r++) acc[mi][ni][r]=0.f;

    const int px = t>>1, halfsel = t&1;
    const uint32_t b_rowbase = (uint32_t)px*128u + (uint32_t)halfsel*64u;

    // ---- stage loader ----
    auto LOAD = [&](int s){
        int buf = s&1;
        int term = s/36, rem = s%36, chunk = rem/9, tap = rem%9;
        int dy = tap/3, dx = tap%3;
        int aplane = (term==2)?1:0, bplane = (term==1)?1:0;
        const char* asrc = (const char*)(g_wA +
            ((size_t)((((which*2+aplane)*4+chunk)*9+tap)*2 + ochalf))*8192) + t*64;
        uint32_t ad = sb + buf*32768 + t*64;
        #pragma unroll
        for (int i=0;i<4;i++) cp16(ad + i*16, asrc + i*16, 16);

        const __half* ip = bplane ? inL : inH;
        int iy = y+dy-1, ix = px+dx-1;
        int ok = ((unsigned)iy<128u && (unsigned)ix<128u) ? 16 : 0;
        long off = ((long)b*HW + (long)iy*WDIM + ix);
        const char* bsrc = ok ? (const char*)(ip + (off<<8) + chunk*64 + halfsel*32)
                              : (const char*)ip;
        uint32_t bb = sb + buf*32768 + 16384;
        #pragma unroll
        for (int i=0;i<4;i++) cp16(bb + SWZ128(b_rowbase + i*16), bsrc + i*16, ok);
        CP_COMMIT();
    };

    const int arow = wm*64 + (lane&15);
    const int akb  = ((lane>>4)<<4);
    const int brow = wn*32 + (lane&7);
    const int bkb  = (((lane>>3)&1)<<4);

    auto COMPUTE = [&](int buf){
        uint32_t abase = sb + buf*32768;
        uint32_t bbase = abase + 16384;
        #pragma unroll
        for (int ki=0; ki<4; ki++){
            uint32_t a[4][4], bf[4][2];
            #pragma unroll
            for (int mi=0;mi<4;mi++)
                ldsm_x4(a[mi], abase + SWZ128((uint32_t)(arow+mi*16)*128u + ki*32 + akb));
            #pragma unroll
            for (int ni=0;ni<4;ni++)
                ldsm_x2(bf[ni], bbase + SWZ128((uint32_t)(brow+ni*8)*128u + ki*32 + bkb));
            #pragma unroll
            for (int mi=0;mi<4;mi++)
                #pragma unroll
                for (int ni=0;ni<4;ni++)
                    mma16816(acc[mi][ni], a[mi], bf[ni]);
        }
    };

    LOAD(0); LOAD(1);
    for (int s=0;s<108;s++){
        if (s<107) { CP_WAIT(1); } else { CP_WAIT(0); }
        __syncthreads();
        COMPUTE(s&1);
        __syncthreads();
        if (s+2<108) LOAD(s+2);
    }

    // ---- epilogue ----
    if (which==0){
        __half* shh = (__half*)smem;            // [128 px][128 oc]
        __half* shl = (__half*)(smem + 32768);
        #pragma unroll
        for (int mi=0;mi<4;mi++){
            int oc0 = wm*64+mi*16+(lane>>2);
            float s0 = g_bns[0][ochalf*128+oc0],   bb0 = g_bnb[0][ochalf*128+oc0];
            float s8 = g_bns[0][ochalf*128+oc0+8], bb8 = g_bnb[0][ochalf*128+oc0+8];
            #pragma unroll
            for (int ni=0;ni<4;ni++){
                int p0 = wn*32+ni*8+2*(lane&3);
                float v; __half h;
                v = fmaxf(fmaf(acc[mi][ni][0], s0, bb0), 0.f);
                h = __float2half_rn(v); shh[p0*128+oc0]=h;     shl[p0*128+oc0]=__float2half_rn(v-__half2float(h));
                v = fmaxf(fmaf(acc[mi][ni][1], s0, bb0), 0.f);
                h = __float2half_rn(v); shh[(p0+1)*128+oc0]=h; shl[(p0+1)*128+oc0]=__float2half_rn(v-__half2float(h));
                v = fmaxf(fmaf(acc[mi][ni][2], s8, bb8), 0.f);
                h = __float2half_rn(v); shh[p0*128+oc0+8]=h;   shl[p0*128+oc0+8]=__float2half_rn(v-__half2float(h));
                v = fmaxf(fmaf(acc[mi][ni][3], s8, bb8), 0.f);
                h = __float2half_rn(v); shh[(p0+1)*128+oc0+8]=h; shl[(p0+1)*128+oc0+8]=__float2half_rn(v-__half2float(h));
            }
        }
        __syncthreads();
        size_t go = (((size_t)b*HW + (size_t)y*WDIM + px)<<8) + ochalf*128 + halfsel*64;
        const float4* srcH = (const float4*)(shh + px*128 + halfsel*64);
        const float4* srcL = (const float4*)(shl + px*128 + halfsel*64);
        float4* dH = (float4*)(g_feat_hi + go);
        float4* dL = (float4*)(g_feat_lo + go);
        #pragma unroll
        for (int i=0;i<8;i++){ dH[i]=srcH[i]; dL[i]=srcL[i]; }
    } else {
        // fused BN+ReLU+1x1 partial dot (per oc-half), heatmap partials in f32
        float psum[4][2];
        #pragma unroll
        for (int ni=0;ni<4;ni++){ psum[ni][0]=0.f; psum[ni][1]=0.f; }
        #pragma unroll
        for (int mi=0;mi<4;mi++){
            int oc0 = ochalf*128 + wm*64+mi*16+(lane>>2);
            float s0=g_bns[1][oc0],   bb0=g_bnb[1][oc0],   w0=w2[oc0];
            float s8=g_bns[1][oc0+8], bb8=g_bnb[1][oc0+8], w8=w2[oc0+8];
            #pragma unroll
            for (int ni=0;ni<4;ni++){
                psum[ni][0] += fmaxf(fmaf(acc[mi][ni][0],s0,bb0),0.f)*w0
                             + fmaxf(fmaf(acc[mi][ni][2],s8,bb8),0.f)*w8;
                psum[ni][1] += fmaxf(fmaf(acc[mi][ni][1],s0,bb0),0.f)*w0
                             + fmaxf(fmaf(acc[mi][ni][3],s8,bb8),0.f)*w8;
            }
        }
        #pragma unroll
        for (int ni=0;ni<4;ni++)
            #pragma unroll
            for (int o=0;o<2;o++){
                psum[ni][o] += __shfl_xor_sync(0xffffffffu, psum[ni][o], 4);
                psum[ni][o] += __shfl_xor_sync(0xffffffffu, psum[ni][o], 8);
                psum[ni][o] += __shfl_xor_sync(0xffffffffu, psum[ni][o], 16);
            }
        float* spx = (float*)smem;              // [2 wm][128 px]
        if ((lane>>2)==0){
            #pragma unroll
            for (int ni=0;ni<4;ni++){
                int p = wn*32+ni*8+2*lane;
                spx[wm*128+p]   = psum[ni][0];
                spx[wm*128+p+1] = psum[ni][1];
            }
        }
        __syncthreads();
        if (t<128)
            g_hm_part[ochalf][(size_t)b*HW + (size_t)y*WDIM + t] = spx[t] + spx[128+t];
    }
}

// ---------------- top-100 per batch (sorted desc, index-asc ties) ----------
__global__ void topk_kernel(const float* __restrict__ ob2, float* __restrict__ out_score){
    const int b = blockIdx.x;
    const int t = threadIdx.x;   // 512 threads
    const float bias = ob2[0];
    float v[32];
    #pragma unroll
    for (int j=0;j<32;j++){
        size_t o = (size_t)b*HW + j*512 + t;
        float lg = g_hm_part[0][o] + g_hm_part[1][o] + bias;
        v[j] = 1.f/(1.f+expf(-lg));
    }

    __shared__ float s_bv[16];
    __shared__ int   s_bi[16];
    __shared__ int   s_ci;

    for (int k=0;k<KTOP;k++){
        float bv = -1e30f; int bi = 0x7fffffff;
        #pragma unroll
        for (int j=0;j<32;j++){
            float x = v[j]; int idx = j*512+t;
            if (x > bv || (x==bv && idx<bi)) { bv=x; bi=idx; }
        }
        #pragma unroll
        for (int o=16;o>0;o>>=1){
            float ov = __shfl_down_sync(0xffffffffu, bv, o);
            int   oi = __shfl_down_sync(0xffffffffu, bi, o);
            if (ov > bv || (ov==bv && oi<bi)) { bv=ov; bi=oi; }
        }
        if ((t&31)==0){ s_bv[t>>5]=bv; s_bi[t>>5]=bi; }
        __syncthreads();
        if (t==0){
            float cv=s_bv[0]; int ci=s_bi[0];
            for (int w=1;w<16;w++){
                float ov=s_bv[w]; int oi=s_bi[w];
                if (ov>cv || (ov==cv && oi<ci)){cv=ov;ci=oi;}
            }
            s_ci = ci;
            g_tk_score[b*KTOP+k]=cv;
            g_tk_idx  [b*KTOP+k]=ci;
            out_score [b*KTOP+k]=cv;
        }
        __syncthreads();
        int ci = s_ci;
        if ((ci & 511) == t) v[ci>>9] = -1e30f;
        __syncthreads();
    }
}

// ---------------- gather + MLP + LN + heads + anchor ------------------------
__global__ __launch_bounds__(256)
void final_kernel(const float* __restrict__ ta,
                  const float* __restrict__ fw1, const float* __restrict__ fb1,
                  const float* __restrict__ lng, const float* __restrict__ lnb,
                  const float* __restrict__ fw2, const float* __restrict__ fb2,
                  const float* __restrict__ zw,  const float* __restrict__ zb,
                  const float* __restrict__ dw,  const float* __restrict__ db,
                  const float* __restrict__ yw,  const float* __restrict__ yb,
                  const float* __restrict__ vw,  const float* __restrict__ vb,
                  float* __restrict__ out)
{
    const int blk = blockIdx.x;
    const int b = blk/KTOP, k = blk%KTOP;
    const int t = threadIdx.x;

    __shared__ float sg[CDIM];
    __shared__ float sx[CDIM];
    __shared__ float r1[8], r2[8];
    __shared__ float shead[8];

    const int   idx   = g_tk_idx  [b*KTOP+k];
    const float score = g_tk_score[b*KTOP+k];

    {
        size_t o = (((size_t)b*HW + idx) << 8) + t;
        sg[t] = __half2float(g_feat_hi[o]) + __half2float(g_feat_lo[o]);
    }
    __syncthreads();

    float acc = fb1[t];
    {
        const float4* wr = (const float4*)(fw1 + (size_t)t*CDIM);
        #pragma unroll 8
        for (int c4=0; c4<CDIM/4; c4++){
            float4 w = wr[c4];
            acc = fmaf(w.x, sg[c4*4+0], acc);
            acc = fmaf(w.y, sg[c4*4+1], acc);
            acc = fmaf(w.z, sg[c4*4+2], acc);
            acc = fmaf(w.w, sg[c4*4+3], acc);
        }
    }
    {
        float s = acc, ss = acc*acc;
        #pragma unroll
        for (int o=16;o>0;o>>=1){
            s  += __shfl_down_sync(0xffffffffu, s,  o);
            ss += __shfl_down_sync(0xffffffffu, ss, o);
        }
        if ((t&31)==0){ r1[t>>5]=s; r2[t>>5]=ss; }
    }
    __syncthreads();
    float tot=0.f, tot2=0.f;
    #pragma unroll
    for (int i=0;i<8;i++){ tot+=r1[i]; tot2+=r2[i]; }
    float mu  = tot * (1.f/CDIM);
    float var = tot2 * (1.f/CDIM) - mu*mu;
    float xn  = (acc-mu)*rsqrtf(var+1e-5f)*lng[t] + lnb[t];
    xn = fmaxf(xn, 0.f);
    sx[t] = xn;
    __syncthreads();

    float acc2 = fb2[t];
    {
        const float4* wr = (const float4*)(fw2 + (size_t)t*CDIM);
        #pragma unroll 8
        for (int c4=0; c4<CDIM/4; c4++){
            float4 w = wr[c4];
            acc2 = fmaf(w.x, sx[c4*4+0], acc2);
            acc2 = fmaf(w.y, sx[c4*4+1], acc2);
            acc2 = fmaf(w.z, sx[c4*4+2], acc2);
            acc2 = fmaf(w.w, sx[c4*4+3], acc2);
        }
    }
    acc2 *= (1.f + score);
    out[((size_t)(b*KTOP+k))*CDIM + t] = acc2;

    {
        int w = t>>5, lane = t&31;
        const float* hw;
        if      (w==0) hw = zw;
        else if (w<4)  hw = dw + (w-1)*CDIM;
        else if (w<6)  hw = yw + (w-4)*CDIM;
        else           hw = vw + (w-6)*CDIM;
        float hs = 0.f;
        #pragma unroll
        for (int c=0;c<CDIM/32;c++) hs = fmaf(sg[c*32+lane], hw[c*32+lane], hs);
        #pragma unroll
        for (int o=16;o>0;o>>=1) hs += __shfl_down_sync(0xffffffffu, hs, o);
        if (lane==0) shead[w]=hs;
    }
    __syncthreads();

    if (t==0){
        float zp  = shead[0]+zb[0];
        float d0  = shead[1]+db[0], d1 = shead[2]+db[1], d2 = shead[3]+db[2];
        float yp0 = shead[4]+yb[0], yp1 = shead[5]+yb[1];
        float vp0 = shead[6]+vb[0], vp1 = shead[7]+vb[1];
        const float* pa = ta + ((size_t)b*900 + k)*11;
        int xs = idx & 127, ys = idx >> 7;
        float y0 = tanhf(yp0), y1 = tanhf(yp1);
        float nr = fmaxf(sqrtf(y0*y0+y1*y1), 1e-6f);
        float o0 = (xs+0.5f)*0.8f - 51.2f;
        float o1 = (ys+0.5f)*0.8f - 51.2f;
        float* oa = out + 102400 + ((size_t)(b*KTOP+k))*11;
        oa[0]=o0; oa[1]=o1;
        oa[2]=pa[2] + 0.5f*zp;
        oa[3]=pa[3] + 0.2f*fminf(fmaxf(d0,-1.f),1.f);
        oa[4]=pa[4] + 0.2f*fminf(fmaxf(d1,-1.f),1.f);
        oa[5]=pa[5] + 0.2f*fminf(fmaxf(d2,-1.f),1.f);
        oa[6]=0.7f*pa[6] + 0.3f*y0/nr;
        oa[7]=0.7f*pa[7] + 0.3f*y1/nr;
        oa[8]=pa[8] + 0.2f*fminf(fmaxf(vp0,-2.f),2.f);
        oa[9]=pa[9] + 0.2f*fminf(fmaxf(vp1,-2.f),2.f);
        oa[10]=pa[10];
    }
}

// ---------------- launch ----------------------------------------------------
extern "C" void kernel_launch(void* const* d_in, const int* in_sizes, int n_in,
                              void* d_out, int out_size)
{
    const float* bev  = (const float*)d_in[0];
    const float* ta   = (const float*)d_in[1];
    const float* sw   = (const float*)d_in[2];
    const float* bn1g = (const float*)d_in[3];
    const float* bn1b = (const float*)d_in[4];
    const float* bn1m = (const float*)d_in[5];
    const float* bn1v = (const float*)d_in[6];
    const float* ow1  = (const float*)d_in[7];
    const float* bn2g = (const float*)d_in[8];
    const float* bn2b = (const float*)d_in[9];
    const float* bn2m = (const float*)d_in[10];
    const float* bn2v = (const float*)d_in[11];
    const float* ow2  = (const float*)d_in[12];
    const float* ob2  = (const float*)d_in[13];
    const float* fw1  = (const float*)d_in[14];
    const float* fb1  = (const float*)d_in[15];
    const float* lng  = (const float*)d_in[16];
    const float* lnb  = (const float*)d_in[17];
    const float* fw2  = (const float*)d_in[18];
    const float* fb2  = (const float*)d_in[19];
    const float* zw   = (const float*)d_in[20];
    const float* zb   = (const float*)d_in[21];
    const float* dw   = (const float*)d_in[22];
    const float* db   = (const float*)d_in[23];
    const float* yw   = (const float*)d_in[24];
    const float* yb   = (const float*)d_in[25];
    const float* vw   = (const float*)d_in[26];
    const float* vb   = (const float*)d_in[27];

    float* out = (float*)d_out;

    static int smem_set = 0;
    if (!smem_set){
        cudaFuncSetAttribute(conv_mma_kernel,
                             cudaFuncAttributeMaxDynamicSharedMemorySize, 65536);
        smem_set = 1;
    }

    prep_bn_kernel<<<1,256>>>(bn1g,bn1b,bn1m,bn1v, bn2g,bn2b,bn2m,bn2v);
    prep_w_kernel<<<4608,256>>>(sw, ow1);
    transpose_bev_kernel<<<dim3(128,4),256>>>(bev);

    dim3 cgrid(HDIM, 2, BATCH);
    conv_mma_kernel<<<cgrid,256,65536>>>(0, ow2);
    conv_mma_kernel<<<cgrid,256,65536>>>(1, ow2);

    topk_kernel<<<4,512>>>(ob2, out + 102400 + 4400);
    final_kernel<<<400,256>>>(ta, fw1, fb1, lng, lnb, fw2, fb2,
                              zw, zb, dw, db, yw, yb, vw, vb, out);
}